// round 9
// baseline (speedup 1.0000x reference)
#include <cuda_runtime.h>
#include <cuda_fp16.h>
#include <mma.h>
#include <cstdint>
#include <cstddef>

using namespace nvcuda;

// ---------------- problem dims ----------------
#define NQ   4096
#define MKV  4096
#define RD   144
#define LD   3584
#define NH   4
#define HDIM 36
#define HPAD 40
#define VHD  896

// ---------------- scratch ----------------
__device__ __align__(16) __half g_th  [NQ * RD];
__device__ __align__(16) __half g_srch[MKV * LD];
__device__ __align__(16) __half g_valh[MKV * LD];
__device__ __align__(16) __half g_wqh [RD * RD];
__device__ __align__(16) __half g_wkh [LD * RD];
__device__ __align__(16) __half g_resh[RD * LD];
__device__ __align__(16) __half g_outh[LD * LD];
__device__ __align__(16) __half g_Bvh [LD * LD];
__device__ __align__(16) float  g_bv  [LD];
__device__ __align__(16) float  g_Q   [NQ * RD];
__device__ __align__(16) float  g_K   [MKV * RD];
__device__ __align__(16) __half g_Qp  [NH * NQ * HPAD];
__device__ __align__(16) __half g_Kp  [NH * HPAD * MKV];
__device__ __align__(16) __half g_Sh  [(size_t)NH * NQ * MKV];
__device__ __align__(16) __half g_Vh  [MKV * LD];
__device__ __align__(16) float  g_X   [NQ * LD];
__device__ __align__(16) __half g_Yh  [NQ * LD];

// ---------------- cp.async helpers ----------------
__device__ __forceinline__ uint32_t smem_u32(const void* p) {
    uint32_t a;
    asm("{ .reg .u64 t; cvta.to.shared.u64 t, %1; cvt.u32.u64 %0, t; }" : "=r"(a) : "l"(p));
    return a;
}
__device__ __forceinline__ void cp16(uint32_t dst, const void* src, int nbytes) {
    asm volatile("cp.async.cg.shared.global [%0], [%1], 16, %2;"
                 :: "r"(dst), "l"(src), "r"(nbytes) : "memory");
}
#define CP_COMMIT() asm volatile("cp.async.commit_group;" ::: "memory")
#define CP_WAIT(n)  asm volatile("cp.async.wait_group %0;" :: "n"(n) : "memory")

// ---------------- fp16 WMMA GEMM (fp32 accumulate) ----------------
// C[M,N] = alpha * A[M,K] @ B[K,N] (+ bias[n]) (+ C if acc, fp32 out).
// BMT x 128 CTA tile, NWARP = (BMT>=256 ? 8 : 4) warps of 64-wide warp tiles.
constexpr int BN = 128, BK = 32;
constexpr int LDAS = 40;               // halfs
constexpr int LDBS = 136;              // halfs
constexpr int BSTG = BK * LDBS;        // 4352 halfs
constexpr int STAGES = 3;

__host__ __device__ constexpr int nwarp_of(int bmt) { return bmt >= 256 ? 8 : 4; }
__host__ __device__ constexpr int smemb(int bmt) {
    int pipe = STAGES * (bmt * LDAS + BSTG) * 2;
    int rp   = bmt > 128 ? 128 : bmt;
    int cs   = rp * 132 * 4;
    return pipe > cs ? pipe : cs;
}

template<int BMT, int NT>
__device__ __forceinline__ void load_stage(const __half* __restrict__ A,
                                           const __half* __restrict__ B,
                                           uint32_t sa, uint32_t sbb,
                                           int m0, int n0, int kbase,
                                           int N, int K, int lda, int ldb, int tid)
{
    // A tile: BMT rows x 32 halfs = BMT*4 16B chunks
#pragma unroll
    for (int i = 0; i < BMT * 4 / NT; i++) {
        int f = tid + i * NT;
        int r = f >> 2, c = f & 3;
        int gk = kbase + c * 8;
        const __half* src = A + (size_t)(m0 + r) * lda + (gk < K ? gk : 0);
        int nb = (gk < K) ? 16 : 0;
        cp16(sa + (r * LDAS + c * 8) * 2, src, nb);
    }
    // B tile: 32 k-rows x 128 halfs = 512 chunks
#pragma unroll
    for (int i = 0; i < 512 / NT; i++) {
        int f = tid + i * NT;
        int kr = f >> 4, c = f & 15;
        int gk = kbase + kr;
        int gn = n0 + c * 8;
        const __half* src = B + (size_t)(gk < K ? gk : K - 1) * ldb + (gn < N ? gn : 0);
        int nb = (gk < K && gn < N) ? 16 : 0;
        cp16(sbb + (kr * LDBS + c * 8) * 2, src, nb);
    }
}

template<int BMT>
__global__ __launch_bounds__(nwarp_of(BMT) * 32, 2)
void gemm_h(const __half* __restrict__ A, const __half* __restrict__ B,
            void* __restrict__ Cv, const float* __restrict__ bias,
            int M, int N, int K, int lda, int ldb, int ldc,
            long long sA, long long sB, long long sC,
            float alpha, int acc, int outhalf)
{
    constexpr int NWARP = nwarp_of(BMT);
    constexpr int NT    = NWARP * 32;
    constexpr int WROWS = NWARP / 2;         // warp-rows (2 warp-cols of 64)
    constexpr int WM    = BMT / WROWS;       // 64 (or 32 for BMT=64)
    constexpr int AI    = WM / 16;
    constexpr int ASTG  = BMT * LDAS;
    constexpr int EPASS = BMT > 128 ? 2 : 1;
    constexpr int RP    = BMT / EPASS;       // epilogue rows per pass

    extern __shared__ char smem_raw[];
    __half* As = (__half*)smem_raw;
    __half* Bs = As + STAGES * ASTG;
    const uint32_t sa_u = smem_u32(As);
    const uint32_t sb_u = smem_u32(Bs);

    const int tid  = threadIdx.x;
    const int warp = tid >> 5;
    const int wm   = warp % WROWS;
    const int wn   = warp / WROWS;
    const int m0   = blockIdx.y * BMT;
    const int n0   = blockIdx.x * BN;

    A += (size_t)blockIdx.z * sA;
    B += (size_t)blockIdx.z * sB;
    float*  Cf = (float*)Cv  + (size_t)blockIdx.z * sC;
    __half* Ch = (__half*)Cv + (size_t)blockIdx.z * sC;

    wmma::fragment<wmma::accumulator, 16, 16, 16, float> cf[AI][4];
#pragma unroll
    for (int i = 0; i < AI; i++)
#pragma unroll
        for (int j = 0; j < 4; j++)
            wmma::fill_fragment(cf[i][j], 0.f);

    const int KT = (K + BK - 1) / BK;

    load_stage<BMT, NT>(A, B, sa_u, sb_u, m0, n0, 0, N, K, lda, ldb, tid);
    CP_COMMIT();
    if (KT > 1)
        load_stage<BMT, NT>(A, B, sa_u + ASTG * 2, sb_u + BSTG * 2,
                            m0, n0, BK, N, K, lda, ldb, tid);
    CP_COMMIT();

    int cur = 0, nxt = 2;
#pragma unroll 1
    for (int kt = 0; kt < KT; kt++) {
        CP_WAIT(1);
        __syncthreads();

        const __half* ap = As + cur * ASTG + wm * WM * LDAS;
        const __half* bp = Bs + cur * BSTG + wn * 64;
#pragma unroll
        for (int ks = 0; ks < 2; ks++) {
            wmma::fragment<wmma::matrix_a, 16, 16, 16, __half, wmma::row_major> af[AI];
            wmma::fragment<wmma::matrix_b, 16, 16, 16, __half, wmma::row_major> bf[4];
#pragma unroll
            for (int i = 0; i < AI; i++)
                wmma::load_matrix_sync(af[i], ap + (i * 16) * LDAS + ks * 16, LDAS);
#pragma unroll
            for (int j = 0; j < 4; j++)
                wmma::load_matrix_sync(bf[j], bp + (ks * 16) * LDBS + j * 16, LDBS);
#pragma unroll
            for (int i = 0; i < AI; i++)
#pragma unroll
                for (int j = 0; j < 4; j++)
                    wmma::mma_sync(cf[i][j], af[i], bf[j], cf[i][j]);
        }

        int t = kt + 2;
        if (t < KT)
            load_stage<BMT, NT>(A, B, sa_u + nxt * ASTG * 2, sb_u + nxt * BSTG * 2,
                                m0, n0, t * BK, N, K, lda, ldb, tid);
        CP_COMMIT();

        cur = (cur == 2) ? 0 : cur + 1;
        nxt = (nxt == 2) ? 0 : nxt + 1;
    }

    __syncthreads();

    // epilogue: EPASS passes of RP rows staged through fp32 smem
    float* Cs = (float*)smem_raw;   // RP x 132 floats
#pragma unroll 1
    for (int p = 0; p < EPASS; p++) {
        const int rbase = p * RP;
        if (wm * WM >= rbase && wm * WM < rbase + RP) {
#pragma unroll
            for (int i = 0; i < AI; i++)
#pragma unroll
                for (int j = 0; j < 4; j++)
                    wmma::store_matrix_sync(Cs + (wm * WM - rbase + i * 16) * 132 + wn * 64 + j * 16,
                                            cf[i][j], 132, wmma::mem_row_major);
        }
        __syncthreads();

#pragma unroll 1
        for (int e = tid; e < RP * 32; e += NT) {
            int rr = e >> 5, c4 = (e & 31) << 2;
            int gm = m0 + rbase + rr, gn = n0 + c4;
            if (gn < N) {
                float4 v = *reinterpret_cast<float4*>(&Cs[rr * 132 + c4]);
                v.x *= alpha; v.y *= alpha; v.z *= alpha; v.w *= alpha;
                if (bias) {
                    float4 bv = *reinterpret_cast<const float4*>(bias + gn);
                    v.x += bv.x; v.y += bv.y; v.z += bv.z; v.w += bv.w;
                }
                if (outhalf) {
                    __half* cp = Ch + (size_t)gm * ldc + gn;
                    *reinterpret_cast<__half2*>(cp)     = __floats2half2_rn(v.x, v.y);
                    *reinterpret_cast<__half2*>(cp + 2) = __floats2half2_rn(v.z, v.w);
                } else {
                    float* cp = Cf + (size_t)gm * ldc + gn;
                    if (acc) {
                        float4 o = *reinterpret_cast<float4*>(cp);
                        v.x += o.x; v.y += o.y; v.z += o.z; v.w += o.w;
                    }
                    *reinterpret_cast<float4*>(cp) = v;
                }
            }
        }
        if (p + 1 < EPASS) __syncthreads();
    }
}

// ---------------- fp32 -> fp16 convert ----------------
__global__ void f2h_k(const float* __restrict__ in, __half* __restrict__ out, int n)
{
    int i = (blockIdx.x * 256 + threadIdx.x) * 4;
    if (i >= n) return;
    float4 v = *reinterpret_cast<const float4*>(in + i);
    *reinterpret_cast<__half2*>(out + i)     = __floats2half2_rn(v.x, v.y);
    *reinterpret_cast<__half2*>(out + i + 2) = __floats2half2_rn(v.z, v.w);
}

// ---------------- repack per-head V weights ----------------
__global__ void pack_v_k(const float* __restrict__ wv, const float* __restrict__ wvb,
                         __half* __restrict__ Bv, float* __restrict__ bv)
{
    int idx = blockIdx.x * 256 + threadIdx.x;
    if (idx >= LD * LD) return;
    int k = idx / LD, n = idx % LD;
    int h = n / VHD, d = n % VHD;
    Bv[idx] = __float2half_rn(wv[((size_t)h * LD + k) * VHD + d]);
    if (k == 0) bv[n] = wvb[h * VHD + d];
}

// ---------------- pad head dim 36->40 (fp16) ----------------
__global__ void pad_qk_k(const float* __restrict__ Q, const float* __restrict__ Ks,
                         __half* __restrict__ Qp, __half* __restrict__ Kp)
{
    int idx = blockIdx.x * 256 + threadIdx.x;
    if (idx >= NH * NQ * HPAD) return;
    int k = idx % HPAD;
    int n = (idx / HPAD) % NQ;
    int h = idx / (HPAD * NQ);
    float q = 0.f, kk = 0.f;
    if (k < HDIM) {
        q  = Q [n * RD + h * HDIM + k];
        kk = Ks[n * RD + h * HDIM + k];
    }
    Qp[idx] = __float2half_rn(q);
    Kp[((size_t)h * HPAD + k) * MKV + n] = __float2half_rn(kk);
}

// ---------------- row softmax over 4096 fp16, in place ----------------
__global__ void softmax_h(__half* __restrict__ S)
{
    const int row = blockIdx.x;
    const int h   = blockIdx.y;
    __half2* p = reinterpret_cast<__half2*>(S + ((size_t)(h * NQ + row)) * MKV);
    const int tid = threadIdx.x;

    float2 x[8];
#pragma unroll
    for (int i = 0; i < 8; i++) x[i] = __half22float2(p[tid + (i << 8)]);

    float mx = -1e30f;
#pragma unroll
    for (int i = 0; i < 8; i++) mx = fmaxf(mx, fmaxf(x[i].x, x[i].y));
#pragma unroll
    for (int o = 16; o > 0; o >>= 1) mx = fmaxf(mx, __shfl_xor_sync(0xffffffffu, mx, o));
    __shared__ float rmax[8], rsum[8];
    if ((tid & 31) == 0) rmax[tid >> 5] = mx;
    __syncthreads();
    mx = rmax[0];
#pragma unroll
    for (int i = 1; i < 8; i++) mx = fmaxf(mx, rmax[i]);

    float s = 0.f;
    float2 e[8];
#pragma unroll
    for (int i = 0; i < 8; i++) {
        e[i].x = __expf(x[i].x - mx);
        e[i].y = __expf(x[i].y - mx);
        s += e[i].x + e[i].y;
    }
#pragma unroll
    for (int o = 16; o > 0; o >>= 1) s += __shfl_xor_sync(0xffffffffu, s, o);
    if ((tid & 31) == 0) rsum[tid >> 5] = s;
    __syncthreads();
    s = rsum[0];
#pragma unroll
    for (int i = 1; i < 8; i++) s += rsum[i];

    const float inv = 1.f / s;
#pragma unroll
    for (int i = 0; i < 8; i++)
        p[tid + (i << 8)] = __floats2half2_rn(e[i].x * inv, e[i].y * inv);
}

// ---------------- LayerNorm over 3584, fp32 in -> fp16 out ----------------
__global__ void ln_k(const float* __restrict__ X, __half* __restrict__ Y,
                     const float* __restrict__ g, const float* __restrict__ b)
{
    const int row = blockIdx.x;
    const float* xr = X + (size_t)row * LD;
    __half*      yr = Y + (size_t)row * LD;
    const int tid = threadIdx.x;

    float x[14];
#pragma unroll
    for (int i = 0; i < 14; i++) x[i] = xr[tid + (i << 8)];

    float s = 0.f;
#pragma unroll
    for (int i = 0; i < 14; i++) s += x[i];
#pragma unroll
    for (int o = 16; o > 0; o >>= 1) s += __shfl_xor_sync(0xffffffffu, s, o);
    __shared__ float r1[8], r2[8];
    if ((tid & 31) == 0) r1[tid >> 5] = s;
    __syncthreads();
    s = 0.f;
#pragma unroll
    for (int i = 0; i < 8; i++) s += r1[i];
    const float mu = s * (1.f / LD);

    float vs = 0.f;
#pragma unroll
    for (int i = 0; i < 14; i++) { float d = x[i] - mu; vs += d * d; }
#pragma unroll
    for (int o = 16; o > 0; o >>= 1) vs += __shfl_xor_sync(0xffffffffu, vs, o);
    if ((tid & 31) == 0) r2[tid >> 5] = vs;
    __syncthreads();
    vs = 0.f;
#pragma unroll
    for (int i = 0; i < 8; i++) vs += r2[i];
    const float inv = rsqrtf(vs * (1.f / LD) + 1e-5f);

#pragma unroll
    for (int i = 0; i < 14; i++) {
        int c = tid + (i << 8);
        yr[c] = __float2half_rn((x[i] - mu) * inv * g[c] + b[c]);
    }
}

// ---------------- host launcher ----------------
template<int BMT>
static inline void launch_gemm(const __half* A, const __half* B, void* C, const float* bias,
                               int M, int N, int K, int lda, int ldb, int ldc,
                               long long sA, long long sB, long long sC, int batch,
                               float alpha, int acc, int outhalf)
{
    dim3 grid((N + BN - 1) / BN, M / BMT, batch);
    gemm_h<BMT><<<grid, nwarp_of(BMT) * 32, smemb(BMT)>>>(
        A, B, C, bias, M, N, K, lda, ldb, ldc, sA, sB, sC, alpha, acc, outhalf);
}

static inline void f2h(const float* in, __half* out, int n)
{
    f2h_k<<<(n / 4 + 255) / 256, 256>>>(in, out, n);
}

extern "C" void kernel_launch(void* const* d_in, const int* in_sizes, int n_in,
                              void* d_out, int out_size)
{
    (void)in_sizes; (void)n_in; (void)out_size;
    const float* target  = (const float*)d_in[0];
    const float* source  = (const float*)d_in[1];
    const float* value   = (const float*)d_in[2];
    const float* wq_w    = (const float*)d_in[3];
    const float* wq_b    = (const float*)d_in[4];
    const float* wk_w    = (const float*)d_in[5];
    const float* wk_b    = (const float*)d_in[6];
    const float* wv_w    = (const float*)d_in[7];
    const float* wv_b    = (const float*)d_in[8];
    const float* resid_w = (const float*)d_in[9];
    const float* resid_b = (const float*)d_in[10];
    const float* out_w   = (const float*)d_in[11];
    const float* out_b   = (const float*)d_in[12];
    const float* ln_g    = (const float*)d_in[13];
    const float* ln_b    = (const float*)d_in[14];
    float* out = (float*)d_out;

    cudaFuncSetAttribute((const void*)gemm_h<256>,
                         cudaFuncAttributeMaxDynamicSharedMemorySize, smemb(256));
    cudaFuncSetAttribute((const void*)gemm_h<64>,
                         cudaFuncAttributeMaxDynamicSharedMemorySize, smemb(64));

    __half *pth, *psrch, *pvalh, *pwqh, *pwkh, *presh, *pouth, *pBvh, *pQp, *pKp, *pSh, *pVh, *pYh;
    float *pbv, *pQ, *pK, *pX;
    cudaGetSymbolAddress((void**)&pth,   g_th);
    cudaGetSymbolAddress((void**)&psrch, g_srch);
    cudaGetSymbolAddress((void**)&pvalh, g_valh);
    cudaGetSymbolAddress((void**)&pwqh,  g_wqh);
    cudaGetSymbolAddress((void**)&pwkh,  g_wkh);
    cudaGetSymbolAddress((void**)&presh, g_resh);
    cudaGetSymbolAddress((void**)&pouth, g_outh);
    cudaGetSymbolAddress((void**)&pBvh,  g_Bvh);
    cudaGetSymbolAddress((void**)&pbv,   g_bv);
    cudaGetSymbolAddress((void**)&pQ,    g_Q);
    cudaGetSymbolAddress((void**)&pK,    g_K);
    cudaGetSymbolAddress((void**)&pQp,   g_Qp);
    cudaGetSymbolAddress((void**)&pKp,   g_Kp);
    cudaGetSymbolAddress((void**)&pSh,   g_Sh);
    cudaGetSymbolAddress((void**)&pVh,   g_Vh);
    cudaGetSymbolAddress((void**)&pX,    g_X);
    cudaGetSymbolAddress((void**)&pYh,   g_Yh);

    // 0) fp32 -> fp16 conversions
    f2h(target,  pth,   NQ * RD);
    f2h(source,  psrch, MKV * LD);
    f2h(value,   pvalh, MKV * LD);
    f2h(wq_w,    pwqh,  RD * RD);
    f2h(wk_w,    pwkh,  LD * RD);
    f2h(resid_w, presh, RD * LD);
    f2h(out_w,   pouth, LD * LD);
    pack_v_k<<<(LD * LD + 255) / 256, 256>>>(wv_w, wv_b, pBvh, pbv);

    // 1) Q = target @ wq_w + wq_b         [4096,144] fp32
    launch_gemm<64>(pth, pwqh, pQ, wq_b, NQ, RD, RD, RD, RD, RD, 0, 0, 0, 1, 1.f, 0, 0);

    // 2) K = source @ wk_w + wk_b         [4096,144] fp32
    launch_gemm<64>(psrch, pwkh, pK, wk_b, MKV, RD, LD, LD, RD, RD, 0, 0, 0, 1, 1.f, 0, 0);

    // 3) pad + transpose per head (fp16 out)
    pad_qk_k<<<(NH * NQ * HPAD + 255) / 256, 256>>>(pQ, pK, pQp, pKp);

    // 4) scores[h] = (Qp[h] @ Kp[h]) / 6  -> fp16 S
    launch_gemm<256>(pQp, pKp, pSh, nullptr, NQ, MKV, HPAD,
                     HPAD, MKV, MKV,
                     (long long)NQ * HPAD, (long long)HPAD * MKV, (long long)NQ * MKV,
                     NH, 1.f / 6.f, 0, 1);

    // 5) softmax rows (fp16 in place)
    softmax_h<<<dim3(NQ, NH), 256>>>(pSh);

    // 6) V = value @ Bv + bv              -> fp16 [4096,3584]
    launch_gemm<256>(pvalh, pBvh, pVh, pbv, MKV, LD, LD, LD, LD, LD, 0, 0, 0, 1, 1.f, 0, 1);

    // 7) ctx[h] = P[h] @ V[:, h*896:(h+1)*896]  -> fp32 X columns
    launch_gemm<256>(pSh, pVh, pX, nullptr, NQ, VHD, MKV,
                     MKV, LD, LD,
                     (long long)NQ * MKV, (long long)VHD, (long long)VHD,
                     NH, 1.f, 0, 0);

    // 8) X += target @ resid_w + resid_b  (fp32 accumulate)
    launch_gemm<256>(pth, presh, pX, resid_b, NQ, LD, RD, RD, LD, LD, 0, 0, 0, 1, 1.f, 1, 0);

    // 9) LayerNorm -> fp16 Y
    ln_k<<<NQ, 256>>>(pX, pYh, ln_g, ln_b);

    // 10) out = Y @ out_w + out_b         -> fp32
    launch_gemm<256>(pYh, pouth, out, out_b, NQ, LD, LD, LD, LD, LD, 0, 0, 0, 1, 1.f, 0, 0);
}

// round 12
// speedup vs baseline: 2.3577x; 2.3577x over previous
#include <cuda_runtime.h>
#include <cuda_fp16.h>
#include <mma.h>
#include <cstdint>
#include <cstddef>

using namespace nvcuda;

// ---------------- problem dims ----------------
#define NQ   4096
#define MKV  4096
#define RD   144
#define LD   3584
#define NH   4
#define HDIM 36
#define HPAD 40
#define VHD  896

// ---------------- scratch ----------------
__device__ __align__(16) __half g_th  [NQ * RD];
__device__ __align__(16) __half g_srch[MKV * LD];
__device__ __align__(16) __half g_valh[MKV * LD];
__device__ __align__(16) __half g_wqh [RD * RD];
__device__ __align__(16) __half g_wkh [LD * RD];
__device__ __align__(16) __half g_resh[RD * LD];
__device__ __align__(16) __half g_outh[LD * LD];
__device__ __align__(16) __half g_Bvh [LD * LD];
__device__ __align__(16) float  g_bv  [LD];
__device__ __align__(16) float  g_Q   [NQ * RD];
__device__ __align__(16) float  g_K   [MKV * RD];
__device__ __align__(16) __half g_Qp  [NH * NQ * HPAD];
__device__ __align__(16) __half g_Kp  [NH * HPAD * MKV];
__device__ __align__(16) __half g_Sh  [(size_t)NH * NQ * MKV];
__device__ __align__(16) __half g_Vh  [MKV * LD];
__device__ __align__(16) float  g_X   [NQ * LD];
__device__ __align__(16) __half g_Yh  [NQ * LD];

// ---------------- cp.async helpers ----------------
__device__ __forceinline__ uint32_t smem_u32(const void* p) {
    uint32_t a;
    asm("{ .reg .u64 t; cvta.to.shared.u64 t, %1; cvt.u32.u64 %0, t; }" : "=r"(a) : "l"(p));
    return a;
}
__device__ __forceinline__ void cp16(uint32_t dst, const void* src, int nbytes) {
    asm volatile("cp.async.cg.shared.global [%0], [%1], 16, %2;"
                 :: "r"(dst), "l"(src), "r"(nbytes) : "memory");
}
#define CP_COMMIT() asm volatile("cp.async.commit_group;" ::: "memory")
#define CP_WAIT(n)  asm volatile("cp.async.wait_group %0;" :: "n"(n) : "memory")

// ---------------- fp16 WMMA GEMM (fp32 accumulate), BMTx128x64, 4 warps ----------------
// C[M,N] = alpha * A[M,K] @ B[K,N] (+ bias[n]) (+ C if acc, fp32 out).
// A, B fp16 row-major. Output fp32 (outhalf=0) or fp16 (outhalf=1).
constexpr int BN = 128, BK = 64;
constexpr int LDAS = 72;               // halfs (64 + 8 pad)
constexpr int LDBS = 136;              // halfs (128 + 8 pad)
constexpr int BSTG = BK * LDBS;        // 8704 halfs per B stage
constexpr int STAGES = 3;

__host__ __device__ constexpr int astg_h(int bmt) { return bmt * LDAS; }
__host__ __device__ constexpr int smemb(int bmt) {
    int pipe = STAGES * (astg_h(bmt) + BSTG) * 2;
    int cs   = bmt * 132 * 4;
    return pipe > cs ? pipe : cs;
}

template<int BMT>
__device__ __forceinline__ void load_stage(const __half* __restrict__ A,
                                           const __half* __restrict__ B,
                                           uint32_t sa, uint32_t sbb,
                                           int m0, int n0, int kbase,
                                           int N, int K, int lda, int ldb, int tid)
{
    // A tile: BMT rows x 64 halfs (8 chunks of 8). BMT*8/128 per thread.
#pragma unroll
    for (int i = 0; i < BMT / 16; i++) {
        int f = tid + i * 128;
        int r = f >> 3, c = f & 7;
        int gk = kbase + c * 8;
        const __half* src = A + (size_t)(m0 + r) * lda + (gk < K ? gk : 0);
        int nb = (gk < K) ? 16 : 0;
        cp16(sa + (r * LDAS + c * 8) * 2, src, nb);
    }
    // B tile: 64 k-rows x 128 halfs (16 chunks of 8). 8 per thread.
#pragma unroll
    for (int i = 0; i < 8; i++) {
        int f = tid + i * 128;
        int kr = f >> 4, c = f & 15;
        int gk = kbase + kr;
        int gn = n0 + c * 8;
        const __half* src = B + (size_t)(gk < K ? gk : K - 1) * ldb + (gn < N ? gn : 0);
        int nb = (gk < K && gn < N) ? 16 : 0;
        cp16(sbb + (kr * LDBS + c * 8) * 2, src, nb);
    }
}

template<int BMT>
__global__ __launch_bounds__(128, 2)
void gemm_h(const __half* __restrict__ A, const __half* __restrict__ B,
            void* __restrict__ Cv, const float* __restrict__ bias,
            int M, int N, int K, int lda, int ldb, int ldc,
            long long sA, long long sB, long long sC,
            float alpha, int acc, int outhalf)
{
    constexpr int WM   = BMT / 2;
    constexpr int AI   = WM / 16;
    constexpr int ASTG = BMT * LDAS;

    extern __shared__ char smem_raw[];
    __half* As = (__half*)smem_raw;
    __half* Bs = As + STAGES * ASTG;
    const uint32_t sa_u = smem_u32(As);
    const uint32_t sb_u = smem_u32(Bs);

    const int tid  = threadIdx.x;
    const int warp = tid >> 5;
    const int wm   = warp & 1;
    const int wn   = warp >> 1;
    const int m0   = blockIdx.y * BMT;
    const int n0   = blockIdx.x * BN;

    A += (size_t)blockIdx.z * sA;
    B += (size_t)blockIdx.z * sB;
    float*  Cf = (float*)Cv  + (size_t)blockIdx.z * sC;
    __half* Ch = (__half*)Cv + (size_t)blockIdx.z * sC;

    wmma::fragment<wmma::accumulator, 16, 16, 16, float> cf[AI][4];
#pragma unroll
    for (int i = 0; i < AI; i++)
#pragma unroll
        for (int j = 0; j < 4; j++)
            wmma::fill_fragment(cf[i][j], 0.f);

    const int KT = (K + BK - 1) / BK;

    load_stage<BMT>(A, B, sa_u, sb_u, m0, n0, 0, N, K, lda, ldb, tid);
    CP_COMMIT();
    if (KT > 1)
        load_stage<BMT>(A, B, sa_u + ASTG * 2, sb_u + BSTG * 2,
                        m0, n0, BK, N, K, lda, ldb, tid);
    CP_COMMIT();

    int cur = 0, nxt = 2;
#pragma unroll 1
    for (int kt = 0; kt < KT; kt++) {
        CP_WAIT(1);
        __syncthreads();

        const __half* ap = As + cur * ASTG + wm * WM * LDAS;
        const __half* bp = Bs + cur * BSTG + wn * 64;
#pragma unroll
        for (int ks = 0; ks < 4; ks++) {
            wmma::fragment<wmma::matrix_a, 16, 16, 16, __half, wmma::row_major> af[AI];
            wmma::fragment<wmma::matrix_b, 16, 16, 16, __half, wmma::row_major> bf[4];
#pragma unroll
            for (int i = 0; i < AI; i++)
                wmma::load_matrix_sync(af[i], ap + (i * 16) * LDAS + ks * 16, LDAS);
#pragma unroll
            for (int j = 0; j < 4; j++)
                wmma::load_matrix_sync(bf[j], bp + (ks * 16) * LDBS + j * 16, LDBS);
#pragma unroll
            for (int i = 0; i < AI; i++)
#pragma unroll
                for (int j = 0; j < 4; j++)
                    wmma::mma_sync(cf[i][j], af[i], bf[j], cf[i][j]);
        }

        int t = kt + 2;
        if (t < KT)
            load_stage<BMT>(A, B, sa_u + nxt * ASTG * 2, sb_u + nxt * BSTG * 2,
                            m0, n0, t * BK, N, K, lda, ldb, tid);
        CP_COMMIT();

        cur = (cur == 2) ? 0 : cur + 1;
        nxt = (nxt == 2) ? 0 : nxt + 1;
    }

    __syncthreads();

    // epilogue via fp32 smem staging
    float* Cs = (float*)smem_raw;   // BMT x 132 floats
#pragma unroll
    for (int i = 0; i < AI; i++)
#pragma unroll
        for (int j = 0; j < 4; j++)
            wmma::store_matrix_sync(Cs + (wm * WM + i * 16) * 132 + wn * 64 + j * 16,
                                    cf[i][j], 132, wmma::mem_row_major);
    __syncthreads();

#pragma unroll 1
    for (int e = tid; e < BMT * 32; e += 128) {
        int rr = e >> 5, c4 = (e & 31) << 2;
        int gm = m0 + rr, gn = n0 + c4;
        if (gn >= N) continue;
        float4 v = *reinterpret_cast<float4*>(&Cs[rr * 132 + c4]);
        v.x *= alpha; v.y *= alpha; v.z *= alpha; v.w *= alpha;
        if (bias) {
            float4 bv = *reinterpret_cast<const float4*>(bias + gn);
            v.x += bv.x; v.y += bv.y; v.z += bv.z; v.w += bv.w;
        }
        if (outhalf) {
            __half* cp = Ch + (size_t)gm * ldc + gn;
            *reinterpret_cast<__half2*>(cp)     = __floats2half2_rn(v.x, v.y);
            *reinterpret_cast<__half2*>(cp + 2) = __floats2half2_rn(v.z, v.w);
        } else {
            float* cp = Cf + (size_t)gm * ldc + gn;
            if (acc) {
                float4 o = *reinterpret_cast<float4*>(cp);
                v.x += o.x; v.y += o.y; v.z += o.z; v.w += o.w;
            }
            *reinterpret_cast<float4*>(cp) = v;
        }
    }
}

// ---------------- fp32 -> fp16 convert ----------------
__global__ void f2h_k(const float* __restrict__ in, __half* __restrict__ out, int n)
{
    int i = (blockIdx.x * 256 + threadIdx.x) * 4;
    if (i >= n) return;
    float4 v = *reinterpret_cast<const float4*>(in + i);
    *reinterpret_cast<__half2*>(out + i)     = __floats2half2_rn(v.x, v.y);
    *reinterpret_cast<__half2*>(out + i + 2) = __floats2half2_rn(v.z, v.w);
}

// ---------------- repack per-head V weights ----------------
__global__ void pack_v_k(const float* __restrict__ wv, const float* __restrict__ wvb,
                         __half* __restrict__ Bv, float* __restrict__ bv)
{
    int idx = blockIdx.x * 256 + threadIdx.x;
    if (idx >= LD * LD) return;
    int k = idx / LD, n = idx % LD;
    int h = n / VHD, d = n % VHD;
    Bv[idx] = __float2half_rn(wv[((size_t)h * LD + k) * VHD + d]);
    if (k == 0) bv[n] = wvb[h * VHD + d];
}

// ---------------- pad head dim 36->40 (fp16) ----------------
__global__ void pad_qk_k(const float* __restrict__ Q, const float* __restrict__ Ks,
                         __half* __restrict__ Qp, __half* __restrict__ Kp)
{
    int idx = blockIdx.x * 256 + threadIdx.x;
    if (idx >= NH * NQ * HPAD) return;
    int k = idx % HPAD;
    int n = (idx / HPAD) % NQ;
    int h = idx / (HPAD * NQ);
    float q = 0.f, kk = 0.f;
    if (k < HDIM) {
        q  = Q [n * RD + h * HDIM + k];
        kk = Ks[n * RD + h * HDIM + k];
    }
    Qp[idx] = __float2half_rn(q);
    Kp[((size_t)h * HPAD + k) * MKV + n] = __float2half_rn(kk);
}

// ---------------- row softmax over 4096 fp16, in place ----------------
__global__ void softmax_h(__half* __restrict__ S)
{
    const int row = blockIdx.x;
    const int h   = blockIdx.y;
    __half2* p = reinterpret_cast<__half2*>(S + ((size_t)(h * NQ + row)) * MKV);
    const int tid = threadIdx.x;

    float2 x[8];
#pragma unroll
    for (int i = 0; i < 8; i++) x[i] = __half22float2(p[tid + (i << 8)]);

    float mx = -1e30f;
#pragma unroll
    for (int i = 0; i < 8; i++) mx = fmaxf(mx, fmaxf(x[i].x, x[i].y));
#pragma unroll
    for (int o = 16; o > 0; o >>= 1) mx = fmaxf(mx, __shfl_xor_sync(0xffffffffu, mx, o));
    __shared__ float rmax[8], rsum[8];
    if ((tid & 31) == 0) rmax[tid >> 5] = mx;
    __syncthreads();
    mx = rmax[0];
#pragma unroll
    for (int i = 1; i < 8; i++) mx = fmaxf(mx, rmax[i]);

    float s = 0.f;
    float2 e[8];
#pragma unroll
    for (int i = 0; i < 8; i++) {
        e[i].x = __expf(x[i].x - mx);
        e[i].y = __expf(x[i].y - mx);
        s += e[i].x + e[i].y;
    }
#pragma unroll
    for (int o = 16; o > 0; o >>= 1) s += __shfl_xor_sync(0xffffffffu, s, o);
    if ((tid & 31) == 0) rsum[tid >> 5] = s;
    __syncthreads();
    s = rsum[0];
#pragma unroll
    for (int i = 1; i < 8; i++) s += rsum[i];

    const float inv = 1.f / s;
#pragma unroll
    for (int i = 0; i < 8; i++)
        p[tid + (i << 8)] = __floats2half2_rn(e[i].x * inv, e[i].y * inv);
}

// ---------------- LayerNorm over 3584, fp32 in -> fp16 out ----------------
__global__ void ln_k(const float* __restrict__ X, __half* __restrict__ Y,
                     const float* __restrict__ g, const float* __restrict__ b)
{
    const int row = blockIdx.x;
    const float* xr = X + (size_t)row * LD;
    __half*      yr = Y + (size_t)row * LD;
    const int tid = threadIdx.x;

    float x[14];
#pragma unroll
    for (int i = 0; i < 14; i++) x[i] = xr[tid + (i << 8)];

    float s = 0.f;
#pragma unroll
    for (int i = 0; i < 14; i++) s += x[i];
#pragma unroll
    for (int o = 16; o > 0; o >>= 1) s += __shfl_xor_sync(0xffffffffu, s, o);
    __shared__ float r1[8], r2[8];
    if ((tid & 31) == 0) r1[tid >> 5] = s;
    __syncthreads();
    s = 0.f;
#pragma unroll
    for (int i = 0; i < 8; i++) s += r1[i];
    const float mu = s * (1.f / LD);

    float vs = 0.f;
#pragma unroll
    for (int i = 0; i < 14; i++) { float d = x[i] - mu; vs += d * d; }
#pragma unroll
    for (int o = 16; o > 0; o >>= 1) vs += __shfl_xor_sync(0xffffffffu, vs, o);
    if ((tid & 31) == 0) r2[tid >> 5] = vs;
    __syncthreads();
    vs = 0.f;
#pragma unroll
    for (int i = 0; i < 8; i++) vs += r2[i];
    const float inv = rsqrtf(vs * (1.f / LD) + 1e-5f);

#pragma unroll
    for (int i = 0; i < 14; i++) {
        int c = tid + (i << 8);
        yr[c] = __float2half_rn((x[i] - mu) * inv * g[c] + b[c]);
    }
}

// ---------------- host launcher ----------------
template<int BMT>
static inline void launch_gemm(const __half* A, const __half* B, void* C, const float* bias,
                               int M, int N, int K, int lda, int ldb, int ldc,
                               long long sA, long long sB, long long sC, int batch,
                               float alpha, int acc, int outhalf)
{
    dim3 grid((N + BN - 1) / BN, M / BMT, batch);
    gemm_h<BMT><<<grid, 128, smemb(BMT)>>>(A, B, C, bias, M, N, K, lda, ldb, ldc,
                                           sA, sB, sC, alpha, acc, outhalf);
}

static inline void f2h(const float* in, __half* out, int n)
{
    f2h_k<<<(n / 4 + 255) / 256, 256>>>(in, out, n);
}

extern "C" void kernel_launch(void* const* d_in, const int* in_sizes, int n_in,
                              void* d_out, int out_size)
{
    (void)in_sizes; (void)n_in; (void)out_size;
    const float* target  = (const float*)d_in[0];
    const float* source  = (const float*)d_in[1];
    const float* value   = (const float*)d_in[2];
    const float* wq_w    = (const float*)d_in[3];
    const float* wq_b    = (const float*)d_in[4];
    const float* wk_w    = (const float*)d_in[5];
    const float* wk_b    = (const float*)d_in[6];
    const float* wv_w    = (const float*)d_in[7];
    const float* wv_b    = (const float*)d_in[8];
    const float* resid_w = (const float*)d_in[9];
    const float* resid_b = (const float*)d_in[10];
    const float* out_w   = (const float*)d_in[11];
    const float* out_b   = (const float*)d_in[12];
    const float* ln_g    = (const float*)d_in[13];
    const float* ln_b    = (const float*)d_in[14];
    float* out = (float*)d_out;

    cudaFuncSetAttribute((const void*)gemm_h<128>,
                         cudaFuncAttributeMaxDynamicSharedMemorySize, smemb(128));
    cudaFuncSetAttribute((const void*)gemm_h<64>,
                         cudaFuncAttributeMaxDynamicSharedMemorySize, smemb(64));

    __half *pth, *psrch, *pvalh, *pwqh, *pwkh, *presh, *pouth, *pBvh, *pQp, *pKp, *pSh, *pVh, *pYh;
    float *pbv, *pQ, *pK, *pX;
    cudaGetSymbolAddress((void**)&pth,   g_th);
    cudaGetSymbolAddress((void**)&psrch, g_srch);
    cudaGetSymbolAddress((void**)&pvalh, g_valh);
    cudaGetSymbolAddress((void**)&pwqh,  g_wqh);
    cudaGetSymbolAddress((void**)&pwkh,  g_wkh);
    cudaGetSymbolAddress((void**)&presh, g_resh);
    cudaGetSymbolAddress((void**)&pouth, g_outh);
    cudaGetSymbolAddress((void**)&pBvh,  g_Bvh);
    cudaGetSymbolAddress((void**)&pbv,   g_bv);
    cudaGetSymbolAddress((void**)&pQ,    g_Q);
    cudaGetSymbolAddress((void**)&pK,    g_K);
    cudaGetSymbolAddress((void**)&pQp,   g_Qp);
    cudaGetSymbolAddress((void**)&pKp,   g_Kp);
    cudaGetSymbolAddress((void**)&pSh,   g_Sh);
    cudaGetSymbolAddress((void**)&pVh,   g_Vh);
    cudaGetSymbolAddress((void**)&pX,    g_X);
    cudaGetSymbolAddress((void**)&pYh,   g_Yh);

    // 0) fp32 -> fp16 conversions
    f2h(target,  pth,   NQ * RD);
    f2h(source,  psrch, MKV * LD);
    f2h(value,   pvalh, MKV * LD);
    f2h(wq_w,    pwqh,  RD * RD);
    f2h(wk_w,    pwkh,  LD * RD);
    f2h(resid_w, presh, RD * LD);
    f2h(out_w,   pouth, LD * LD);
    pack_v_k<<<(LD * LD + 255) / 256, 256>>>(wv_w, wv_b, pBvh, pbv);

    // 1) Q = target @ wq_w + wq_b         [4096,144] fp32
    launch_gemm<64>(pth, pwqh, pQ, wq_b, NQ, RD, RD, RD, RD, RD, 0, 0, 0, 1, 1.f, 0, 0);

    // 2) K = source @ wk_w + wk_b         [4096,144] fp32
    launch_gemm<64>(psrch, pwkh, pK, wk_b, MKV, RD, LD, LD, RD, RD, 0, 0, 0, 1, 1.f, 0, 0);

    // 3) pad + transpose per head (fp16 out)
    pad_qk_k<<<(NH * NQ * HPAD + 255) / 256, 256>>>(pQ, pK, pQp, pKp);

    // 4) scores[h] = (Qp[h] @ Kp[h]) / 6  -> fp16 S   (KT=1 with BK=64)
    launch_gemm<128>(pQp, pKp, pSh, nullptr, NQ, MKV, HPAD,
                     HPAD, MKV, MKV,
                     (long long)NQ * HPAD, (long long)HPAD * MKV, (long long)NQ * MKV,
                     NH, 1.f / 6.f, 0, 1);

    // 5) softmax rows (fp16 in place)
    softmax_h<<<dim3(NQ, NH), 256>>>(pSh);

    // 6) V = value @ Bv + bv              -> fp16 [4096,3584]
    launch_gemm<128>(pvalh, pBvh, pVh, pbv, MKV, LD, LD, LD, LD, LD, 0, 0, 0, 1, 1.f, 0, 1);

    // 7) ctx[h] = P[h] @ V[:, h*896:(h+1)*896]  -> fp32 X columns
    launch_gemm<128>(pSh, pVh, pX, nullptr, NQ, VHD, MKV,
                     MKV, LD, LD,
                     (long long)NQ * MKV, (long long)VHD, (long long)VHD,
                     NH, 1.f, 0, 0);

    // 8) X += target @ resid_w + resid_b  (fp32 accumulate)
    launch_gemm<128>(pth, presh, pX, resid_b, NQ, LD, RD, RD, LD, LD, 0, 0, 0, 1, 1.f, 1, 0);

    // 9) LayerNorm -> fp16 Y
    ln_k<<<NQ, 256>>>(pX, pYh, ln_g, ln_b);

    // 10) out = Y @ out_w + out_b         -> fp32
    launch_gemm<128>(pYh, pouth, out, out_b, NQ, LD, LD, LD, LD, LD, 0, 0, 0, 1, 1.f, 0, 0);
}

// round 15
// speedup vs baseline: 2.4283x; 1.0299x over previous
#include <cuda_runtime.h>
#include <cuda_fp16.h>
#include <mma.h>
#include <cstdint>
#include <cstddef>

using namespace nvcuda;

// ---------------- problem dims ----------------
#define NQ   4096
#define MKV  4096
#define RD   144
#define LD   3584
#define NH   4
#define HDIM 36
#define HPAD 40
#define VHD  896

// ---------------- scratch ----------------
__device__ __align__(16) __half g_th  [NQ * RD];
__device__ __align__(16) __half g_srch[MKV * LD];
__device__ __align__(16) __half g_valh[MKV * LD];
__device__ __align__(16) __half g_wqh [RD * RD];
__device__ __align__(16) __half g_wkh [LD * RD];
__device__ __align__(16) __half g_resh[RD * LD];
__device__ __align__(16) __half g_outh[LD * LD];
__device__ __align__(16) __half g_Bvh [LD * LD];
__device__ __align__(16) float  g_bv  [LD];
__device__ __align__(16) float  g_Q   [NQ * RD];
__device__ __align__(16) float  g_K   [MKV * RD];
__device__ __align__(16) __half g_Qp  [NH * NQ * HPAD];
__device__ __align__(16) __half g_Kp  [NH * HPAD * MKV];
__device__ __align__(16) __half g_Sh  [(size_t)NH * NQ * MKV];
__device__ __align__(16) __half g_Vh  [MKV * LD];
__device__ __align__(16) float  g_X   [NQ * LD];
__device__ __align__(16) __half g_Yh  [NQ * LD];

// ---------------- cp.async helpers ----------------
__device__ __forceinline__ uint32_t smem_u32(const void* p) {
    uint32_t a;
    asm("{ .reg .u64 t; cvta.to.shared.u64 t, %1; cvt.u32.u64 %0, t; }" : "=r"(a) : "l"(p));
    return a;
}
__device__ __forceinline__ void cp16(uint32_t dst, const void* src, int nbytes) {
    asm volatile("cp.async.cg.shared.global [%0], [%1], 16, %2;"
                 :: "r"(dst), "l"(src), "r"(nbytes) : "memory");
}
#define CP_COMMIT() asm volatile("cp.async.commit_group;" ::: "memory")
#define CP_WAIT(n)  asm volatile("cp.async.wait_group %0;" :: "n"(n) : "memory")

// ---------------- fp16 WMMA GEMM (fp32 accumulate), BMTx128x64, 4 warps ----------------
constexpr int BN = 128, BK = 64;
constexpr int LDAS = 72;               // halfs (64 + 8 pad)
constexpr int LDBS = 136;              // halfs (128 + 8 pad)
constexpr int BSTG = BK * LDBS;        // 8704 halfs per B stage
constexpr int STAGES = 3;

__host__ __device__ constexpr int astg_h(int bmt) { return bmt * LDAS; }
__host__ __device__ constexpr int smemb(int bmt) {
    int pipe = STAGES * (astg_h(bmt) + BSTG) * 2;
    int cs   = bmt * 132 * 4;
    return pipe > cs ? pipe : cs;
}

template<int BMT>
__device__ __forceinline__ void load_stage(const __half* __restrict__ A,
                                           const __half* __restrict__ B,
                                           uint32_t sa, uint32_t sbb,
                                           int m0, int n0, int kbase,
                                           int N, int K, int lda, int ldb, int tid)
{
#pragma unroll
    for (int i = 0; i < BMT / 16; i++) {
        int f = tid + i * 128;
        int r = f >> 3, c = f & 7;
        int gk = kbase + c * 8;
        const __half* src = A + (size_t)(m0 + r) * lda + (gk < K ? gk : 0);
        int nb = (gk < K) ? 16 : 0;
        cp16(sa + (r * LDAS + c * 8) * 2, src, nb);
    }
#pragma unroll
    for (int i = 0; i < 8; i++) {
        int f = tid + i * 128;
        int kr = f >> 4, c = f & 15;
        int gk = kbase + kr;
        int gn = n0 + c * 8;
        const __half* src = B + (size_t)(gk < K ? gk : K - 1) * ldb + (gn < N ? gn : 0);
        int nb = (gk < K && gn < N) ? 16 : 0;
        cp16(sbb + (kr * LDBS + c * 8) * 2, src, nb);
    }
}

template<int BMT>
__global__ __launch_bounds__(128, 2)
void gemm_h(const __half* __restrict__ A, const __half* __restrict__ B,
            void* __restrict__ Cv, const float* __restrict__ bias,
            int M, int N, int K, int lda, int ldb, int ldc,
            long long sA, long long sB, long long sC,
            float alpha, int acc, int outhalf)
{
    constexpr int WM   = BMT / 2;
    constexpr int AI   = WM / 16;
    constexpr int ASTG = BMT * LDAS;

    extern __shared__ char smem_raw[];
    __half* As = (__half*)smem_raw;
    __half* Bs = As + STAGES * ASTG;
    const uint32_t sa_u = smem_u32(As);
    const uint32_t sb_u = smem_u32(Bs);

    const int tid  = threadIdx.x;
    const int warp = tid >> 5;
    const int wm   = warp & 1;
    const int wn   = warp >> 1;
    const int m0   = blockIdx.y * BMT;
    const int n0   = blockIdx.x * BN;

    A += (size_t)blockIdx.z * sA;
    B += (size_t)blockIdx.z * sB;
    float*  Cf = (float*)Cv  + (size_t)blockIdx.z * sC;
    __half* Ch = (__half*)Cv + (size_t)blockIdx.z * sC;

    wmma::fragment<wmma::accumulator, 16, 16, 16, float> cf[AI][4];
#pragma unroll
    for (int i = 0; i < AI; i++)
#pragma unroll
        for (int j = 0; j < 4; j++)
            wmma::fill_fragment(cf[i][j], 0.f);

    const int KT = (K + BK - 1) / BK;

    load_stage<BMT>(A, B, sa_u, sb_u, m0, n0, 0, N, K, lda, ldb, tid);
    CP_COMMIT();
    if (KT > 1)
        load_stage<BMT>(A, B, sa_u + ASTG * 2, sb_u + BSTG * 2,
                        m0, n0, BK, N, K, lda, ldb, tid);
    CP_COMMIT();

    int cur = 0, nxt = 2;
#pragma unroll 1
    for (int kt = 0; kt < KT; kt++) {
        CP_WAIT(1);
        __syncthreads();

        const __half* ap = As + cur * ASTG + wm * WM * LDAS;
        const __half* bp = Bs + cur * BSTG + wn * 64;
#pragma unroll
        for (int ks = 0; ks < 4; ks++) {
            wmma::fragment<wmma::matrix_a, 16, 16, 16, __half, wmma::row_major> af[AI];
            wmma::fragment<wmma::matrix_b, 16, 16, 16, __half, wmma::row_major> bf[4];
#pragma unroll
            for (int i = 0; i < AI; i++)
                wmma::load_matrix_sync(af[i], ap + (i * 16) * LDAS + ks * 16, LDAS);
#pragma unroll
            for (int j = 0; j < 4; j++)
                wmma::load_matrix_sync(bf[j], bp + (ks * 16) * LDBS + j * 16, LDBS);
#pragma unroll
            for (int i = 0; i < AI; i++)
#pragma unroll
                for (int j = 0; j < 4; j++)
                    wmma::mma_sync(cf[i][j], af[i], bf[j], cf[i][j]);
        }

        int t = kt + 2;
        if (t < KT)
            load_stage<BMT>(A, B, sa_u + nxt * ASTG * 2, sb_u + nxt * BSTG * 2,
                            m0, n0, t * BK, N, K, lda, ldb, tid);
        CP_COMMIT();

        cur = (cur == 2) ? 0 : cur + 1;
        nxt = (nxt == 2) ? 0 : nxt + 1;
    }

    __syncthreads();

    float* Cs = (float*)smem_raw;   // BMT x 132 floats
#pragma unroll
    for (int i = 0; i < AI; i++)
#pragma unroll
        for (int j = 0; j < 4; j++)
            wmma::store_matrix_sync(Cs + (wm * WM + i * 16) * 132 + wn * 64 + j * 16,
                                    cf[i][j], 132, wmma::mem_row_major);
    __syncthreads();

#pragma unroll 1
    for (int e = tid; e < BMT * 32; e += 128) {
        int rr = e >> 5, c4 = (e & 31) << 2;
        int gm = m0 + rr, gn = n0 + c4;
        if (gn >= N) continue;
        float4 v = *reinterpret_cast<float4*>(&Cs[rr * 132 + c4]);
        v.x *= alpha; v.y *= alpha; v.z *= alpha; v.w *= alpha;
        if (bias) {
            float4 bv = *reinterpret_cast<const float4*>(bias + gn);
            v.x += bv.x; v.y += bv.y; v.z += bv.z; v.w += bv.w;
        }
        if (outhalf) {
            __half* cp = Ch + (size_t)gm * ldc + gn;
            *reinterpret_cast<__half2*>(cp)     = __floats2half2_rn(v.x, v.y);
            *reinterpret_cast<__half2*>(cp + 2) = __floats2half2_rn(v.z, v.w);
        } else {
            float* cp = Cf + (size_t)gm * ldc + gn;
            if (acc) {
                float4 o = *reinterpret_cast<float4*>(cp);
                v.x += o.x; v.y += o.y; v.z += o.z; v.w += o.w;
            }
            *reinterpret_cast<float4*>(cp) = v;
        }
    }
}

// ---------------- fp32 -> fp16 convert ----------------
__global__ void f2h_k(const float* __restrict__ in, __half* __restrict__ out, int n)
{
    int i = (blockIdx.x * 256 + threadIdx.x) * 4;
    if (i >= n) return;
    float4 v = *reinterpret_cast<const float4*>(in + i);
    *reinterpret_cast<__half2*>(out + i)     = __floats2half2_rn(v.x, v.y);
    *reinterpret_cast<__half2*>(out + i + 2) = __floats2half2_rn(v.z, v.w);
}

// ---------------- repack per-head V weights ----------------
__global__ void pack_v_k(const float* __restrict__ wv, const float* __restrict__ wvb,
                         __half* __restrict__ Bv, float* __restrict__ bv)
{
    int idx = blockIdx.x * 256 + threadIdx.x;
    if (idx >= LD * LD) return;
    int k = idx / LD, n = idx % LD;
    int h = n / VHD, d = n % VHD;
    Bv[idx] = __float2half_rn(wv[((size_t)h * LD + k) * VHD + d]);
    if (k == 0) bv[n] = wvb[h * VHD + d];
}

// ---------------- pad head dim 36->40 (fp16) ----------------
__global__ void pad_qk_k(const float* __restrict__ Q, const float* __restrict__ Ks,
                         __half* __restrict__ Qp, __half* __restrict__ Kp)
{
    int idx = blockIdx.x * 256 + threadIdx.x;
    if (idx >= NH * NQ * HPAD) return;
    int k = idx % HPAD;
    int n = (idx / HPAD) % NQ;
    int h = idx / (HPAD * NQ);
    float q = 0.f, kk = 0.f;
    if (k < HDIM) {
        q  = Q [n * RD + h * HDIM + k];
        kk = Ks[n * RD + h * HDIM + k];
    }
    Qp[idx] = __float2half_rn(q);
    Kp[((size_t)h * HPAD + k) * MKV + n] = __float2half_rn(kk);
}

// ---------------- row softmax over 4096 fp16, in place ----------------
__global__ void softmax_h(__half* __restrict__ S)
{
    const int row = blockIdx.x;
    const int h   = blockIdx.y;
    __half2* p = reinterpret_cast<__half2*>(S + ((size_t)(h * NQ + row)) * MKV);
    const int tid = threadIdx.x;

    float2 x[8];
#pragma unroll
    for (int i = 0; i < 8; i++) x[i] = __half22float2(p[tid + (i << 8)]);

    float mx = -1e30f;
#pragma unroll
    for (int i = 0; i < 8; i++) mx = fmaxf(mx, fmaxf(x[i].x, x[i].y));
#pragma unroll
    for (int o = 16; o > 0; o >>= 1) mx = fmaxf(mx, __shfl_xor_sync(0xffffffffu, mx, o));
    __shared__ float rmax[8], rsum[8];
    if ((tid & 31) == 0) rmax[tid >> 5] = mx;
    __syncthreads();
    mx = rmax[0];
#pragma unroll
    for (int i = 1; i < 8; i++) mx = fmaxf(mx, rmax[i]);

    float s = 0.f;
    float2 e[8];
#pragma unroll
    for (int i = 0; i < 8; i++) {
        e[i].x = __expf(x[i].x - mx);
        e[i].y = __expf(x[i].y - mx);
        s += e[i].x + e[i].y;
    }
#pragma unroll
    for (int o = 16; o > 0; o >>= 1) s += __shfl_xor_sync(0xffffffffu, s, o);
    if ((tid & 31) == 0) rsum[tid >> 5] = s;
    __syncthreads();
    s = rsum[0];
#pragma unroll
    for (int i = 1; i < 8; i++) s += rsum[i];

    const float inv = 1.f / s;
#pragma unroll
    for (int i = 0; i < 8; i++)
        p[tid + (i << 8)] = __floats2half2_rn(e[i].x * inv, e[i].y * inv);
}

// ---------------- LayerNorm over 3584, fp32 in -> fp16 out ----------------
__global__ void ln_k(const float* __restrict__ X, __half* __restrict__ Y,
                     const float* __restrict__ g, const float* __restrict__ b)
{
    const int row = blockIdx.x;
    const float* xr = X + (size_t)row * LD;
    __half*      yr = Y + (size_t)row * LD;
    const int tid = threadIdx.x;

    float x[14];
#pragma unroll
    for (int i = 0; i < 14; i++) x[i] = xr[tid + (i << 8)];

    float s = 0.f;
#pragma unroll
    for (int i = 0; i < 14; i++) s += x[i];
#pragma unroll
    for (int o = 16; o > 0; o >>= 1) s += __shfl_xor_sync(0xffffffffu, s, o);
    __shared__ float r1[8], r2[8];
    if ((tid & 31) == 0) r1[tid >> 5] = s;
    __syncthreads();
    s = 0.f;
#pragma unroll
    for (int i = 0; i < 8; i++) s += r1[i];
    const float mu = s * (1.f / LD);

    float vs = 0.f;
#pragma unroll
    for (int i = 0; i < 14; i++) { float d = x[i] - mu; vs += d * d; }
#pragma unroll
    for (int o = 16; o > 0; o >>= 1) vs += __shfl_xor_sync(0xffffffffu, vs, o);
    if ((tid & 31) == 0) r2[tid >> 5] = vs;
    __syncthreads();
    vs = 0.f;
#pragma unroll
    for (int i = 0; i < 8; i++) vs += r2[i];
    const float inv = rsqrtf(vs * (1.f / LD) + 1e-5f);

#pragma unroll
    for (int i = 0; i < 14; i++) {
        int c = tid + (i << 8);
        yr[c] = __float2half_rn((x[i] - mu) * inv * g[c] + b[c]);
    }
}

// ---------------- host launcher ----------------
template<int BMT>
static inline void launch_gemm(cudaStream_t st,
                               const __half* A, const __half* B, void* C, const float* bias,
                               int M, int N, int K, int lda, int ldb, int ldc,
                               long long sA, long long sB, long long sC, int batch,
                               float alpha, int acc, int outhalf)
{
    dim3 grid((N + BN - 1) / BN, M / BMT, batch);
    gemm_h<BMT><<<grid, 128, smemb(BMT), st>>>(A, B, C, bias, M, N, K, lda, ldb, ldc,
                                               sA, sB, sC, alpha, acc, outhalf);
}

static inline void f2h(cudaStream_t st, const float* in, __half* out, int n)
{
    f2h_k<<<(n / 4 + 255) / 256, 256, 0, st>>>(in, out, n);
}

extern "C" void kernel_launch(void* const* d_in, const int* in_sizes, int n_in,
                              void* d_out, int out_size)
{
    (void)in_sizes; (void)n_in; (void)out_size;
    const float* target  = (const float*)d_in[0];
    const float* source  = (const float*)d_in[1];
    const float* value   = (const float*)d_in[2];
    const float* wq_w    = (const float*)d_in[3];
    const float* wq_b    = (const float*)d_in[4];
    const float* wk_w    = (const float*)d_in[5];
    const float* wk_b    = (const float*)d_in[6];
    const float* wv_w    = (const float*)d_in[7];
    const float* wv_b    = (const float*)d_in[8];
    const float* resid_w = (const float*)d_in[9];
    const float* resid_b = (const float*)d_in[10];
    const float* out_w   = (const float*)d_in[11];
    const float* out_b   = (const float*)d_in[12];
    const float* ln_g    = (const float*)d_in[13];
    const float* ln_b    = (const float*)d_in[14];
    float* out = (float*)d_out;

    cudaFuncSetAttribute((const void*)gemm_h<128>,
                         cudaFuncAttributeMaxDynamicSharedMemorySize, smemb(128));
    cudaFuncSetAttribute((const void*)gemm_h<64>,
                         cudaFuncAttributeMaxDynamicSharedMemorySize, smemb(64));

    __half *pth, *psrch, *pvalh, *pwqh, *pwkh, *presh, *pouth, *pBvh, *pQp, *pKp, *pSh, *pVh, *pYh;
    float *pbv, *pQ, *pK, *pX;
    cudaGetSymbolAddress((void**)&pth,   g_th);
    cudaGetSymbolAddress((void**)&psrch, g_srch);
    cudaGetSymbolAddress((void**)&pvalh, g_valh);
    cudaGetSymbolAddress((void**)&pwqh,  g_wqh);
    cudaGetSymbolAddress((void**)&pwkh,  g_wkh);
    cudaGetSymbolAddress((void**)&presh, g_resh);
    cudaGetSymbolAddress((void**)&pouth, g_outh);
    cudaGetSymbolAddress((void**)&pBvh,  g_Bvh);
    cudaGetSymbolAddress((void**)&pbv,   g_bv);
    cudaGetSymbolAddress((void**)&pQ,    g_Q);
    cudaGetSymbolAddress((void**)&pK,    g_K);
    cudaGetSymbolAddress((void**)&pQp,   g_Qp);
    cudaGetSymbolAddress((void**)&pKp,   g_Kp);
    cudaGetSymbolAddress((void**)&pSh,   g_Sh);
    cudaGetSymbolAddress((void**)&pVh,   g_Vh);
    cudaGetSymbolAddress((void**)&pX,    g_X);
    cudaGetSymbolAddress((void**)&pYh,   g_Yh);

    cudaStream_t d0 = 0;
    cudaStream_t s2;
    cudaStreamCreate(&s2);
    cudaEvent_t eFork, eTgt, eJoin;
    cudaEventCreateWithFlags(&eFork, cudaEventDisableTiming);
    cudaEventCreateWithFlags(&eTgt,  cudaEventDisableTiming);
    cudaEventCreateWithFlags(&eJoin, cudaEventDisableTiming);

    // fork point
    cudaEventRecord(eFork, d0);

    // --- branch A (default stream): target convert first (branch B's resid needs it) ---
    f2h(d0, target, pth, NQ * RD);
    cudaEventRecord(eTgt, d0);

    // --- branch B (s2): value/weights converts, pack, V-proj, resid-proj ---
    cudaStreamWaitEvent(s2, eFork, 0);
    f2h(s2, value,   pvalh, MKV * LD);
    f2h(s2, resid_w, presh, RD * LD);
    f2h(s2, out_w,   pouth, LD * LD);
    pack_v_k<<<(LD * LD + 255) / 256, 256, 0, s2>>>(wv_w, wv_b, pBvh, pbv);
    // V = value @ Bv + bv              -> fp16 [4096,3584]
    launch_gemm<128>(s2, pvalh, pBvh, pVh, pbv, MKV, LD, LD, LD, LD, LD,
                     0, 0, 0, 1, 1.f, 0, 1);
    // X = target @ resid_w + resid_b   (writes X; ctx will accumulate)
    cudaStreamWaitEvent(s2, eTgt, 0);
    launch_gemm<128>(s2, pth, presh, pX, resid_b, NQ, LD, RD, RD, LD, LD,
                     0, 0, 0, 1, 1.f, 0, 0);
    cudaEventRecord(eJoin, s2);

    // --- branch A continues: source/wq/wk converts, Q/K proj, pad, scores, softmax ---
    f2h(d0, source, psrch, MKV * LD);
    f2h(d0, wq_w,   pwqh,  RD * RD);
    f2h(d0, wk_w,   pwkh,  LD * RD);
    launch_gemm<64>(d0, pth,   pwqh, pQ, wq_b, NQ,  RD, RD, RD, RD, RD, 0, 0, 0, 1, 1.f, 0, 0);
    launch_gemm<64>(d0, psrch, pwkh, pK, wk_b, MKV, RD, LD, LD, RD, RD, 0, 0, 0, 1, 1.f, 0, 0);
    pad_qk_k<<<(NH * NQ * HPAD + 255) / 256, 256, 0, d0>>>(pQ, pK, pQp, pKp);
    launch_gemm<128>(d0, pQp, pKp, pSh, nullptr, NQ, MKV, HPAD,
                     HPAD, MKV, MKV,
                     (long long)NQ * HPAD, (long long)HPAD * MKV, (long long)NQ * MKV,
                     NH, 1.f / 6.f, 0, 1);
    softmax_h<<<dim3(NQ, NH), 256, 0, d0>>>(pSh);

    // --- join, then tail on default stream ---
    cudaStreamWaitEvent(d0, eJoin, 0);
    // X += ctx: P[h] @ V[:, h*896:(h+1)*896]   (accumulate into resid-filled X)
    launch_gemm<128>(d0, pSh, pVh, pX, nullptr, NQ, VHD, MKV,
                     MKV, LD, LD,
                     (long long)NQ * MKV, (long long)VHD, (long long)VHD,
                     NH, 1.f, 1, 0);
    ln_k<<<NQ, 256, 0, d0>>>(pX, pYh, ln_g, ln_b);
    launch_gemm<128>(d0, pYh, pouth, out, out_b, NQ, LD, LD, LD, LD, LD,
                     0, 0, 0, 1, 1.f, 0, 0);
}